// round 1
// baseline (speedup 1.0000x reference)
#include <cuda_runtime.h>

#define LL   128
#define BSZ  2
#define EE   768
#define HH   12
#define DHH  64
#define EH   384              // E/2
#define BHH  24               // B*H
#define MROWS 256             // L*B

// ---------------- scratch (device globals; no allocation allowed) -----------
__device__ float g_nq[MROWS * EE];          // conv1d(query) output, (L,B,E)
__device__ float g_proj[MROWS * 4 * EH];    // [q | k | v | e] per row, (256,1536)
__device__ float g_dq[BHH * LL];            // dq[m*128 + x]
__device__ float g_dk[BHH * LL];            // dk[m*128 + l]
__device__ float g_de[LL * BHH];            // de[i*24 + s]
__device__ float g_a[MROWS * EE];           // attention output in (L,B,E)
__device__ float g_y[MROWS * EE];           // deconv output

// ---------------- generic register-blocked SGEMM ---------------------------
// MODE 0: nq   = conv(query)              M=256 N=768  K=1536  A=[prev(q)|q], B=conv_w
// MODE 1: proj = [q|k|v from nq, e from entity]  M=256 N=1536 K=768
// MODE 2: y    = deconv(a)                M=256 N=768  K=1536  A=[a|prev(a)], B=deconv_w
// MODE 3: out  = y @ out_w^T + out_b      M=256 N=768  K=768
template<int MODE>
__global__ __launch_bounds__(256)
void gemm_kernel(const float* __restrict__ A0,   // query(0) / entity(1, secondary) / - / -
                 const float* __restrict__ W0,
                 const float* __restrict__ W1,
                 const float* __restrict__ W2,
                 const float* __restrict__ W3,
                 const float* __restrict__ bb0,
                 const float* __restrict__ bb1,
                 const float* __restrict__ bb2,
                 const float* __restrict__ bb3,
                 float* __restrict__ Cout)
{
    constexpr int BM = 64, BN = 64, BK = 16;
    constexpr int N = (MODE == 1) ? 1536 : 768;
    constexpr int K = (MODE == 0 || MODE == 2) ? 1536 : 768;

    __shared__ float As[BK][BM];
    __shared__ float Bs[BN][BK + 1];

    const int bn  = blockIdx.x * BN;
    const int bm  = blockIdx.y * BM;
    const int tid = threadIdx.x;
    const int tx  = tid & 15, ty = tid >> 4;

    float acc[4][4] = {};

    for (int k0 = 0; k0 < K; k0 += BK) {
        // ---- load A tile (BM x BK) ----
        #pragma unroll
        for (int i = 0; i < 4; i++) {
            int e  = i * 256 + tid;
            int r  = e >> 4, kk = e & 15;
            int row = bm + r, k = k0 + kk;
            float v;
            if (MODE == 0) {
                // A = [prev(query) | query]
                if (k < EE) v = (row >= BSZ) ? A0[(row - BSZ) * EE + k] : 0.f;
                else        v = A0[row * EE + (k - EE)];
            } else if (MODE == 1) {
                // columns < 1152 consume nq; columns >= 1152 consume entity
                const float* Ap = (bn >= 3 * EH) ? A0 : g_nq;
                v = Ap[row * EE + k];
            } else if (MODE == 2) {
                // A = [a | prev(a)]
                if (k < EE) v = g_a[row * EE + k];
                else        v = (row >= BSZ) ? g_a[(row - BSZ) * EE + (k - EE)] : 0.f;
            } else {
                v = g_y[row * EE + k];
            }
            As[kk][r] = v;
        }
        // ---- load B tile (BK x BN), stored [o][kk] ----
        #pragma unroll
        for (int i = 0; i < 4; i++) {
            int e   = i * 256 + tid;
            int o_l = e >> 4, kk = e & 15;
            int o = bn + o_l, k = k0 + kk;
            float v;
            if (MODE == 0) {
                // conv_w (E_out, E_in, 2)
                v = (k < EE) ? W0[(o * EE + k) * 2]
                             : W0[(o * EE + (k - EE)) * 2 + 1];
            } else if (MODE == 1) {
                if (o < EH)          v = W0[o * EE + k];
                else if (o < 2 * EH) v = W1[(o - EH) * EE + k];
                else if (o < 3 * EH) v = W2[(o - 2 * EH) * EE + k];
                else                 v = W3[(o - 3 * EH) * EE + k];
            } else if (MODE == 2) {
                // deconv_w (E_in, E_out, 2), contraction over input channel k
                v = (k < EE) ? W0[(k * EE + o) * 2]
                             : W0[((k - EE) * EE + o) * 2 + 1];
            } else {
                v = W0[o * EE + k];   // out_w (E, E) row-major [o][k]
            }
            Bs[o_l][kk] = v;
        }
        __syncthreads();

        #pragma unroll
        for (int kk = 0; kk < BK; kk++) {
            float a[4], b[4];
            #pragma unroll
            for (int i = 0; i < 4; i++) a[i] = As[kk][ty * 4 + i];
            #pragma unroll
            for (int j = 0; j < 4; j++) b[j] = Bs[tx * 4 + j][kk];
            #pragma unroll
            for (int i = 0; i < 4; i++)
                #pragma unroll
                for (int j = 0; j < 4; j++)
                    acc[i][j] = fmaf(a[i], b[j], acc[i][j]);
        }
        __syncthreads();
    }

    // ---- epilogue: +bias, write ----
    float* C = (MODE == 0) ? g_nq : (MODE == 1) ? g_proj : (MODE == 2) ? g_y : Cout;
    #pragma unroll
    for (int i = 0; i < 4; i++) {
        int row = bm + ty * 4 + i;
        #pragma unroll
        for (int j = 0; j < 4; j++) {
            int o = bn + tx * 4 + j;
            float bias;
            if (MODE == 1) {
                if (o < EH)          bias = bb0[o];
                else if (o < 2 * EH) bias = bb1[o - EH];
                else if (o < 3 * EH) bias = bb2[o - 2 * EH];
                else                 bias = bb3[o - 3 * EH];
            } else {
                bias = bb0[o];
            }
            C[row * N + o] = acc[i][j] + bias;
        }
    }
}

// ---------------- dq / dk / de precompute (9216 length-64 dots) -------------
__global__ __launch_bounds__(256)
void dots_kernel(const float* __restrict__ entity,
                 const float* __restrict__ attn_w)
{
    int w    = (blockIdx.x * blockDim.x + threadIdx.x) >> 5;
    int lane = threadIdx.x & 31;
    if (w >= 3 * BHH * LL) return;
    int which = w / (BHH * LL);
    int idx   = w % (BHH * LL);
    float v;
    if (which < 2) {
        int m = idx >> 7, x = idx & 127;
        int b = m / HH, h = m % HH;
        int row = x * BSZ + b;
        int base = (h < 6) ? (row * 1536 + which * EH + h * 64)
                           : (row * 1536 + 3 * EH + (h - 6) * 64);
        const float* wv = attn_w + which * 64;
        v = g_proj[base + lane] * wv[lane] + g_proj[base + lane + 32] * wv[lane + 32];
    } else {
        int i = idx / BHH, s = idx % BHH;
        int b = s / HH, h = s % HH;
        int base = (i * BSZ + b) * EE + h * 64;
        v = entity[base + lane] * attn_w[128 + lane]
          + entity[base + lane + 32] * attn_w[128 + lane + 32];
    }
    #pragma unroll
    for (int off = 16; off; off >>= 1) v += __shfl_down_sync(0xffffffffu, v, off);
    if (lane == 0) {
        if (which == 0)      g_dq[idx] = v;
        else if (which == 1) g_dk[idx] = v;
        else                 g_de[idx] = v;
    }
}

// ---------------- fused scores + leakyrelu + softmax + probs@Ve -------------
__global__ __launch_bounds__(128)
void attn_kernel(const float* __restrict__ attn_b)
{
    __shared__ float sp[128];
    __shared__ float red[128];
    const int i2 = blockIdx.x;
    const int bh = blockIdx.y;
    const int j  = threadIdx.x;

    // flat index into the scrambled (BH, L, L) score tensor
    const int g     = bh * (LL * LL) + i2 * LL + j;
    const int i_src = g / 3072;
    const int rem   = g % 3072;

    float score = g_dq[(rem % BHH) * LL + i_src]
                + g_dk[(rem >> 7) * LL + (rem & 127)]
                + g_de[i_src * BHH + (rem % BHH)]
                - g_de[(rem / BHH) * BHH + (rem % BHH)]
                + attn_b[0];
    score = (score >= 0.f) ? score : 0.01f * score;

    // softmax over j (row of 128)
    red[j] = score; __syncthreads();
    #pragma unroll
    for (int s = 64; s; s >>= 1) {
        if (j < s) red[j] = fmaxf(red[j], red[j + s]);
        __syncthreads();
    }
    float mx = red[0]; __syncthreads();
    float ex = __expf(score - mx);
    sp[j] = ex; red[j] = ex; __syncthreads();
    #pragma unroll
    for (int s = 64; s; s >>= 1) {
        if (j < s) red[j] += red[j + s];
        __syncthreads();
    }
    float inv = 1.f / red[0];
    __syncthreads();

    // attn[bh, i2, d] = sum_j p[j] * ve[bh, j, d]
    const int b = bh / HH, h = bh % HH;
    const int off = (h < 6) ? (2 * EH + h * 64) : (3 * EH + (h - 6) * 64);
    const int d = j & 63, half = j >> 6;
    float accv = 0.f;
    const int j0 = half * 64;
    #pragma unroll 8
    for (int jj = j0; jj < j0 + 64; jj++) {
        accv += sp[jj] * g_proj[(jj * BSZ + b) * 1536 + off + d];
    }
    red[j] = accv; __syncthreads();
    if (j < 64) {
        float total = (red[j] + red[j + 64]) * inv;
        g_a[(i2 * BSZ + b) * EE + h * 64 + d] = total;   // a[l, b, h*64+d]
    }
}

// ---------------- launcher ---------------------------------------------------
extern "C" void kernel_launch(void* const* d_in, const int* in_sizes, int n_in,
                              void* d_out, int out_size)
{
    const float* query    = (const float*)d_in[0];
    const float* entity   = (const float*)d_in[1];
    const float* conv_w   = (const float*)d_in[2];
    const float* conv_b   = (const float*)d_in[3];
    const float* q_w      = (const float*)d_in[4];
    const float* q_b      = (const float*)d_in[5];
    const float* k_w      = (const float*)d_in[6];
    const float* k_b      = (const float*)d_in[7];
    const float* v_w      = (const float*)d_in[8];
    const float* v_b      = (const float*)d_in[9];
    const float* e_w      = (const float*)d_in[10];
    const float* e_b      = (const float*)d_in[11];
    const float* attn_w   = (const float*)d_in[12];
    const float* attn_b   = (const float*)d_in[13];
    const float* deconv_w = (const float*)d_in[14];
    const float* deconv_b = (const float*)d_in[15];
    const float* out_w    = (const float*)d_in[16];
    const float* out_b    = (const float*)d_in[17];
    float* out = (float*)d_out;

    // 1) nq = conv1d(query): N=768, M=256 -> grid (12,4)
    gemm_kernel<0><<<dim3(12, 4), 256>>>(query, conv_w, nullptr, nullptr, nullptr,
                                         conv_b, nullptr, nullptr, nullptr, nullptr);
    // 2) proj = [q|k|v from nq, e from entity]: N=1536 -> grid (24,4)
    gemm_kernel<1><<<dim3(24, 4), 256>>>(entity, q_w, k_w, v_w, e_w,
                                         q_b, k_b, v_b, e_b, nullptr);
    // 3) dq/dk/de tables: 9216 warps, 8 warps/block
    dots_kernel<<<1152, 256>>>(entity, attn_w);
    // 4) fused attention -> g_a
    attn_kernel<<<dim3(LL, BHH), 128>>>(attn_b);
    // 5) y = deconv(a): grid (12,4)
    gemm_kernel<2><<<dim3(12, 4), 256>>>(nullptr, deconv_w, nullptr, nullptr, nullptr,
                                         deconv_b, nullptr, nullptr, nullptr, nullptr);
    // 6) out = y @ out_w^T + out_b: grid (12,4)
    gemm_kernel<3><<<dim3(12, 4), 256>>>(nullptr, out_w, nullptr, nullptr, nullptr,
                                         out_b, nullptr, nullptr, nullptr, out);
}

// round 2
// speedup vs baseline: 1.7279x; 1.7279x over previous
#include <cuda_runtime.h>

#define LL   128
#define BSZ  2
#define EE   768
#define HH   12
#define EH   384              // E/2
#define BHH  24               // B*H

// ---------------- scratch (device globals; no allocation allowed) -----------
__device__ float g_nq[256 * EE];            // conv1d(query) output, (L,B,E)
__device__ float g_proj[256 * 4 * EH];      // [q | k | v | e] per row, (256,1536)
__device__ float g_dq[BHH * LL];
__device__ float g_dk[BHH * LL];
__device__ float g_de[LL * BHH];
__device__ float g_a[256 * EE];             // attention output in (L,B,E)
__device__ float g_y[256 * EE];             // deconv output

// ---------------- packed f32x2 helpers --------------------------------------
#define FMA2(d, a, b) asm("fma.rn.f32x2 %0, %1, %2, %3;" \
                          : "=l"(d) : "l"(a), "l"(b), "l"(d))
#define DUP2(d, s)    asm("mov.b64 %0, {%1, %1};" : "=l"(d) : "f"(s))
#define UNPK(lo, hi, s) asm("mov.b64 {%0, %1}, %2;" : "=f"(lo), "=f"(hi) : "l"(s))

// ---------------- double-buffered f32x2 SGEMM --------------------------------
// MODE 0: nq   = conv(query)      M=256 N=768  K=1536  A=[prev(q)|q],   B=conv_w
// MODE 1: proj = [q|k|v|e]        M=256 N=1536 K=768   A=nq or entity,  B=4 weights
// MODE 2: y    = deconv(a)        M=256 N=768  K=1536  A=[a|prev(a)],   B=deconv_w
// MODE 3: out  = y @ out_w^T      M=256 N=768  K=768
template<int MODE>
__global__ __launch_bounds__(128)
void gemm_kernel(const float* __restrict__ A0,
                 const float* __restrict__ W0,
                 const float* __restrict__ W1,
                 const float* __restrict__ W2,
                 const float* __restrict__ W3,
                 const float* __restrict__ bb0,
                 const float* __restrict__ bb1,
                 const float* __restrict__ bb2,
                 const float* __restrict__ bb3,
                 float* __restrict__ Cout)
{
    constexpr int BM = 64, BN = 32, BK = 16;
    constexpr int N  = (MODE == 1) ? 1536 : 768;
    constexpr int K  = (MODE == 0 || MODE == 2) ? 1536 : 768;
    constexpr int NT = K / BK;

    __shared__ __align__(16) float As[2][BK][BM];
    __shared__ __align__(16) float Bs[2][BK][BN];

    const int bn  = blockIdx.x * BN;
    const int bm  = blockIdx.y * BM;
    const int tid = threadIdx.x;
    const int tx  = tid & 7;      // 8 col-groups * 4 cols
    const int ty  = tid >> 3;     // 16 row-groups * 4 rows

    // ---- global->register tile loaders -------------------------------------
    const int aK   = tid & 15;           // k offset within tile (A)
    const int aRfl = tid >> 4;           // row fragment 0..7
    const int bKf  = tid & 15;           // (modes 0,1,3) k offset within tile
    const int bOfl = tid >> 4;           // (modes 0,1,3) o fragment
    const int bO2  = tid & 31;           // (mode 2) o offset
    const int bK2f = tid >> 5;           // (mode 2) k fragment 0..3

    float ar[8], br[4];

    auto loadA = [&](int t) {
        const int k = t * BK + aK;
        #pragma unroll
        for (int i = 0; i < 8; i++) {
            const int row = bm + i * 8 + aRfl;
            float v;
            if (MODE == 0) {
                if (k < EE) v = (row >= BSZ) ? A0[(row - BSZ) * EE + k] : 0.f;
                else        v = A0[row * EE + (k - EE)];
            } else if (MODE == 1) {
                const float* Ap = (bn >= 3 * EH) ? A0 : g_nq;
                v = Ap[row * EE + k];
            } else if (MODE == 2) {
                if (k < EE) v = g_a[row * EE + k];
                else        v = (row >= BSZ) ? g_a[(row - BSZ) * EE + (k - EE)] : 0.f;
            } else {
                v = g_y[row * EE + k];
            }
            ar[i] = v;
        }
    };

    auto loadB = [&](int t) {
        if (MODE == 2) {
            const int o = bn + bO2;
            #pragma unroll
            for (int i = 0; i < 4; i++) {
                const int k = t * BK + i * 4 + bK2f;
                br[i] = (k < EE) ? W0[(k * EE + o) * 2]
                                 : W0[((k - EE) * EE + o) * 2 + 1];
            }
        } else {
            const int k = t * BK + bKf;
            #pragma unroll
            for (int i = 0; i < 4; i++) {
                const int o = bn + i * 8 + bOfl;
                float v;
                if (MODE == 0) {
                    v = (k < EE) ? W0[(o * EE + k) * 2]
                                 : W0[(o * EE + (k - EE)) * 2 + 1];
                } else if (MODE == 1) {
                    if (o < EH)          v = W0[o * EE + k];
                    else if (o < 2 * EH) v = W1[(o - EH) * EE + k];
                    else if (o < 3 * EH) v = W2[(o - 2 * EH) * EE + k];
                    else                 v = W3[(o - 3 * EH) * EE + k];
                } else {
                    v = W0[o * EE + k];
                }
                br[i] = v;
            }
        }
    };

    auto storeTiles = [&](int nb) {
        #pragma unroll
        for (int i = 0; i < 8; i++) As[nb][aK][i * 8 + aRfl] = ar[i];
        if (MODE == 2) {
            #pragma unroll
            for (int i = 0; i < 4; i++) Bs[nb][i * 4 + bK2f][bO2] = br[i];
        } else {
            #pragma unroll
            for (int i = 0; i < 4; i++) Bs[nb][bKf][i * 8 + bOfl] = br[i];
        }
    };

    unsigned long long acc[4][2] = {};

    loadA(0); loadB(0);
    storeTiles(0);
    __syncthreads();

    int buf = 0;
    for (int t = 0; t < NT; t++) {
        if (t + 1 < NT) { loadA(t + 1); loadB(t + 1); }

        #pragma unroll
        for (int kk = 0; kk < BK; kk++) {
            const unsigned long long bv0 =
                *(const unsigned long long*)&Bs[buf][kk][tx * 4];
            const unsigned long long bv1 =
                *(const unsigned long long*)&Bs[buf][kk][tx * 4 + 2];
            #pragma unroll
            for (int i = 0; i < 4; i++) {
                const float av = As[buf][kk][ty * 4 + i];
                unsigned long long ad;
                DUP2(ad, av);
                FMA2(acc[i][0], ad, bv0);
                FMA2(acc[i][1], ad, bv1);
            }
        }

        if (t + 1 < NT) {
            storeTiles(buf ^ 1);
            __syncthreads();
            buf ^= 1;
        }
    }

    // ---- epilogue: +bias, vector store --------------------------------------
    float* C = (MODE == 0) ? g_nq : (MODE == 1) ? g_proj
             : (MODE == 2) ? g_y  : Cout;
    const int oB = bn + tx * 4;
    float bias[4];
    #pragma unroll
    for (int j = 0; j < 4; j++) {
        const int o = oB + j;
        if (MODE == 1) {
            if (o < EH)          bias[j] = bb0[o];
            else if (o < 2 * EH) bias[j] = bb1[o - EH];
            else if (o < 3 * EH) bias[j] = bb2[o - 2 * EH];
            else                 bias[j] = bb3[o - 3 * EH];
        } else {
            bias[j] = bb0[o];
        }
    }
    #pragma unroll
    for (int i = 0; i < 4; i++) {
        const int row = bm + ty * 4 + i;
        float4 r4;
        UNPK(r4.x, r4.y, acc[i][0]);
        UNPK(r4.z, r4.w, acc[i][1]);
        r4.x += bias[0]; r4.y += bias[1]; r4.z += bias[2]; r4.w += bias[3];
        *(float4*)&C[row * N + oB] = r4;
    }
}

// ---------------- dq / dk / de precompute (9216 length-64 dots) -------------
__global__ __launch_bounds__(256)
void dots_kernel(const float* __restrict__ entity,
                 const float* __restrict__ attn_w)
{
    int w    = (blockIdx.x * blockDim.x + threadIdx.x) >> 5;
    int lane = threadIdx.x & 31;
    if (w >= 3 * BHH * LL) return;
    int which = w / (BHH * LL);
    int idx   = w % (BHH * LL);
    float v;
    if (which < 2) {
        int m = idx >> 7, x = idx & 127;
        int b = m / HH, h = m % HH;
        int row = x * BSZ + b;
        int base = (h < 6) ? (row * 1536 + which * EH + h * 64)
                           : (row * 1536 + 3 * EH + (h - 6) * 64);
        const float* wv = attn_w + which * 64;
        v = g_proj[base + lane] * wv[lane] + g_proj[base + lane + 32] * wv[lane + 32];
    } else {
        int i = idx / BHH, s = idx % BHH;
        int b = s / HH, h = s % HH;
        int base = (i * BSZ + b) * EE + h * 64;
        v = entity[base + lane] * attn_w[128 + lane]
          + entity[base + lane + 32] * attn_w[128 + lane + 32];
    }
    #pragma unroll
    for (int off = 16; off; off >>= 1) v += __shfl_down_sync(0xffffffffu, v, off);
    if (lane == 0) {
        if (which == 0)      g_dq[idx] = v;
        else if (which == 1) g_dk[idx] = v;
        else                 g_de[idx] = v;
    }
}

// ---------------- fused scores + leakyrelu + softmax + probs@Ve -------------
__global__ __launch_bounds__(128)
void attn_kernel(const float* __restrict__ attn_b)
{
    __shared__ float sp[128];
    __shared__ float red[128];
    const int i2 = blockIdx.x;
    const int bh = blockIdx.y;
    const int j  = threadIdx.x;

    const int g     = bh * (LL * LL) + i2 * LL + j;
    const int i_src = g / 3072;
    const int rem   = g % 3072;

    float score = g_dq[(rem % BHH) * LL + i_src]
                + g_dk[(rem >> 7) * LL + (rem & 127)]
                + g_de[i_src * BHH + (rem % BHH)]
                - g_de[(rem / BHH) * BHH + (rem % BHH)]
                + attn_b[0];
    score = (score >= 0.f) ? score : 0.01f * score;

    red[j] = score; __syncthreads();
    #pragma unroll
    for (int s = 64; s; s >>= 1) {
        if (j < s) red[j] = fmaxf(red[j], red[j + s]);
        __syncthreads();
    }
    float mx = red[0]; __syncthreads();
    float ex = __expf(score - mx);
    sp[j] = ex; red[j] = ex; __syncthreads();
    #pragma unroll
    for (int s = 64; s; s >>= 1) {
        if (j < s) red[j] += red[j + s];
        __syncthreads();
    }
    float inv = 1.f / red[0];
    __syncthreads();

    const int b = bh / HH, h = bh % HH;
    const int off = (h < 6) ? (2 * EH + h * 64) : (3 * EH + (h - 6) * 64);
    const int d = j & 63, half = j >> 6;
    float accv = 0.f;
    const int j0 = half * 64;
    #pragma unroll 8
    for (int jj = j0; jj < j0 + 64; jj++) {
        accv += sp[jj] * g_proj[(jj * BSZ + b) * 1536 + off + d];
    }
    red[j] = accv; __syncthreads();
    if (j < 64) {
        float total = (red[j] + red[j + 64]) * inv;
        g_a[(i2 * BSZ + b) * EE + h * 64 + d] = total;
    }
}

// ---------------- launcher ---------------------------------------------------
extern "C" void kernel_launch(void* const* d_in, const int* in_sizes, int n_in,
                              void* d_out, int out_size)
{
    const float* query    = (const float*)d_in[0];
    const float* entity   = (const float*)d_in[1];
    const float* conv_w   = (const float*)d_in[2];
    const float* conv_b   = (const float*)d_in[3];
    const float* q_w      = (const float*)d_in[4];
    const float* q_b      = (const float*)d_in[5];
    const float* k_w      = (const float*)d_in[6];
    const float* k_b      = (const float*)d_in[7];
    const float* v_w      = (const float*)d_in[8];
    const float* v_b      = (const float*)d_in[9];
    const float* e_w      = (const float*)d_in[10];
    const float* e_b      = (const float*)d_in[11];
    const float* attn_w   = (const float*)d_in[12];
    const float* attn_b   = (const float*)d_in[13];
    const float* deconv_w = (const float*)d_in[14];
    const float* deconv_b = (const float*)d_in[15];
    const float* out_w    = (const float*)d_in[16];
    const float* out_b    = (const float*)d_in[17];
    float* out = (float*)d_out;

    // 1) nq = conv1d(query): grid (768/32, 256/64) = (24,4)
    gemm_kernel<0><<<dim3(24, 4), 128>>>(query, conv_w, nullptr, nullptr, nullptr,
                                         conv_b, nullptr, nullptr, nullptr, nullptr);
    // 2) proj: grid (1536/32, 4) = (48,4)
    gemm_kernel<1><<<dim3(48, 4), 128>>>(entity, q_w, k_w, v_w, e_w,
                                         q_b, k_b, v_b, e_b, nullptr);
    // 3) dq/dk/de tables
    dots_kernel<<<1152, 256>>>(entity, attn_w);
    // 4) fused attention -> g_a
    attn_kernel<<<dim3(LL, BHH), 128>>>(attn_b);
    // 5) y = deconv(a): grid (24,4)
    gemm_kernel<2><<<dim3(24, 4), 128>>>(nullptr, deconv_w, nullptr, nullptr, nullptr,
                                         deconv_b, nullptr, nullptr, nullptr, nullptr);
    // 6) out = y @ out_w^T + out_b: grid (24,4)
    gemm_kernel<3><<<dim3(24, 4), 128>>>(nullptr, out_w, nullptr, nullptr, nullptr,
                                         out_b, nullptr, nullptr, nullptr, out);
}

// round 4
// speedup vs baseline: 2.5151x; 1.4556x over previous
#include <cuda_runtime.h>

#define LL   128
#define BSZ  2
#define EE   768
#define HH   12
#define EH   384              // E/2
#define BHH  24               // B*H

// ---------------- scratch (device globals; no allocation allowed) -----------
__device__ float g_nq[256 * EE];            // conv1d(query) output, (L,B,E)
__device__ float g_proj[256 * 4 * EH];      // [q | k | v | e] per row, (256,1536)
__device__ float g_dq[BHH * LL];
__device__ float g_dk[BHH * LL];
__device__ float g_de[LL * BHH];
__device__ float g_a[256 * EE];             // attention output in (L,B,E)
__device__ float g_y[256 * EE];             // deconv output

// ---------------- packed f32x2 helpers --------------------------------------
#define FMA2(d, a, b) asm("fma.rn.f32x2 %0, %1, %2, %3;" \
                          : "=l"(d) : "l"(a), "l"(b), "l"(d))
#define DUP2(d, s)    asm("mov.b64 %0, {%1, %1};" : "=l"(d) : "f"(s))
#define UNPK(lo, hi, s) asm("mov.b64 {%0, %1}, %2;" : "=f"(lo), "=f"(hi) : "l"(s))

// ---------------- double-buffered f32x2 SGEMM --------------------------------
// 256 threads, tile 64x32, BK=16. Rows-packed accumulators:
//   acc[rp][c] : f32x2 over rows (ty*4+2rp, ty*4+2rp+1), col bn+tx*2+c
// MODE 0: nq   = conv(query)      M=256 N=768  K=1536
// MODE 1: proj = [q|k|v|e]        M=256 N=1536 K=768
// MODE 2: y    = deconv(a)        M=256 N=768  K=1536
// MODE 3: out  = y @ out_w^T      M=256 N=768  K=768
template<int MODE>
__global__ __launch_bounds__(256)
void gemm_kernel(const float* __restrict__ A0,
                 const float* __restrict__ W0,
                 const float* __restrict__ W1,
                 const float* __restrict__ W2,
                 const float* __restrict__ W3,
                 const float* __restrict__ bb0,
                 const float* __restrict__ bb1,
                 const float* __restrict__ bb2,
                 const float* __restrict__ bb3,
                 float* __restrict__ Cout)
{
    constexpr int BM = 64, BN = 32, BK = 16;
    constexpr int N  = (MODE == 1) ? 1536 : 768;
    constexpr int K  = (MODE == 0 || MODE == 2) ? 1536 : 768;
    constexpr int NT = K / BK;
    constexpr int ASTR = BM + 4;   // 68: kills the stride-64 bank aliasing
    constexpr int BSTR = BN + 2;   // 34: conflict-free, 8B-aligned rows

    __shared__ __align__(16) float As[2][BK][ASTR];
    __shared__ __align__(16) float Bs[2][BK][BSTR];

    const int bn  = blockIdx.x * BN;
    const int bm  = blockIdx.y * BM;
    const int tid = threadIdx.x;
    const int tx  = tid & 15;     // 16 col-groups * 2 cols
    const int ty  = tid >> 4;     // 16 row-groups * 4 rows

    // loader-owned coordinates
    const int aKK = tid & 15;            // A: k within tile
    const int aTY = tid >> 4;            // A: row fragment base
    const int bKK = tid & 15;            // B (modes 0,1,3)
    const int bTY = tid >> 4;
    const int bO2 = tid & 31;            // B (mode 2)
    const int bK2 = tid >> 5;

    float ar[4], br[2];

    auto loadA = [&](int t) {
        const int k = t * BK + aKK;
        #pragma unroll
        for (int i = 0; i < 4; i++) {
            const int row = bm + i * 16 + aTY;
            float v;
            if (MODE == 0) {
                if (k < EE) v = (row >= BSZ) ? A0[(row - BSZ) * EE + k] : 0.f;
                else        v = A0[row * EE + (k - EE)];
            } else if (MODE == 1) {
                const float* Ap = (bn >= 3 * EH) ? A0 : g_nq;
                v = Ap[row * EE + k];
            } else if (MODE == 2) {
                if (k < EE) v = g_a[row * EE + k];
                else        v = (row >= BSZ) ? g_a[(row - BSZ) * EE + (k - EE)] : 0.f;
            } else {
                v = g_y[row * EE + k];
            }
            ar[i] = v;
        }
    };

    auto loadB = [&](int t) {
        if (MODE == 2) {
            const int o = bn + bO2;
            #pragma unroll
            for (int i = 0; i < 2; i++) {
                const int k = t * BK + i * 8 + bK2;
                br[i] = (k < EE) ? W0[(k * EE + o) * 2]
                                 : W0[((k - EE) * EE + o) * 2 + 1];
            }
        } else {
            const int k = t * BK + bKK;
            #pragma unroll
            for (int i = 0; i < 2; i++) {
                const int o = bn + i * 16 + bTY;
                float v;
                if (MODE == 0) {
                    v = (k < EE) ? W0[(o * EE + k) * 2]
                                 : W0[(o * EE + (k - EE)) * 2 + 1];
                } else if (MODE == 1) {
                    if (o < EH)          v = W0[o * EE + k];
                    else if (o < 2 * EH) v = W1[(o - EH) * EE + k];
                    else if (o < 3 * EH) v = W2[(o - 2 * EH) * EE + k];
                    else                 v = W3[(o - 3 * EH) * EE + k];
                } else {
                    v = W0[o * EE + k];
                }
                br[i] = v;
            }
        }
    };

    auto storeTiles = [&](int nb) {
        #pragma unroll
        for (int i = 0; i < 4; i++) As[nb][aKK][i * 16 + aTY] = ar[i];
        if (MODE == 2) {
            #pragma unroll
            for (int i = 0; i < 2; i++) Bs[nb][i * 8 + bK2][bO2] = br[i];
        } else {
            #pragma unroll
            for (int i = 0; i < 2; i++) Bs[nb][bKK][i * 16 + bTY] = br[i];
        }
    };

    unsigned long long acc[2][2] = {};

    loadA(0); loadB(0);
    storeTiles(0);
    __syncthreads();

    int buf = 0;
    for (int t = 0; t < NT; t++) {
        if (t + 1 < NT) { loadA(t + 1); loadB(t + 1); }

        #pragma unroll
        for (int kk = 0; kk < BK; kk++) {
            const unsigned long long a01 =
                *(const unsigned long long*)&As[buf][kk][ty * 4];
            const unsigned long long a23 =
                *(const unsigned long long*)&As[buf][kk][ty * 4 + 2];
            const float b0 = Bs[buf][kk][tx * 2];
            const float b1 = Bs[buf][kk][tx * 2 + 1];
            unsigned long long bd0, bd1;
            DUP2(bd0, b0); DUP2(bd1, b1);
            FMA2(acc[0][0], a01, bd0);
            FMA2(acc[0][1], a01, bd1);
            FMA2(acc[1][0], a23, bd0);
            FMA2(acc[1][1], a23, bd1);
        }

        if (t + 1 < NT) {
            storeTiles(buf ^ 1);
            __syncthreads();
            buf ^= 1;
        }
    }

    // ---- epilogue: +bias, float2 stores --------------------------------------
    float* C = (MODE == 0) ? g_nq : (MODE == 1) ? g_proj
             : (MODE == 2) ? g_y  : Cout;
    const int oB = bn + tx * 2;
    float bias0, bias1;
    if (MODE == 1) {
        // EH is NOT a power of two: use explicit segment subtraction (R3 bug)
        const int seg = oB / EH;                       // 0..3
        const float* bp = (seg == 0) ? bb0 : (seg == 1) ? bb1
                        : (seg == 2) ? bb2 : bb3;
        const int ob = oB - seg * EH;                  // oB even -> pair in-segment
        bias0 = bp[ob]; bias1 = bp[ob + 1];
    } else {
        bias0 = bb0[oB]; bias1 = bb0[oB + 1];
    }
    #pragma unroll
    for (int rp = 0; rp < 2; rp++) {
        float c0lo, c0hi, c1lo, c1hi;
        UNPK(c0lo, c0hi, acc[rp][0]);
        UNPK(c1lo, c1hi, acc[rp][1]);
        const int r0 = bm + ty * 4 + rp * 2;
        float2 v0 = {c0lo + bias0, c1lo + bias1};
        float2 v1 = {c0hi + bias0, c1hi + bias1};
        *(float2*)&C[r0 * N + oB]       = v0;
        *(float2*)&C[(r0 + 1) * N + oB] = v1;
    }
}

// ---------------- dq / dk / de precompute (9216 length-64 dots) -------------
__global__ __launch_bounds__(256)
void dots_kernel(const float* __restrict__ entity,
                 const float* __restrict__ attn_w)
{
    int w    = (blockIdx.x * blockDim.x + threadIdx.x) >> 5;
    int lane = threadIdx.x & 31;
    if (w >= 3 * BHH * LL) return;
    int which = w / (BHH * LL);
    int idx   = w % (BHH * LL);
    float v;
    if (which < 2) {
        int m = idx >> 7, x = idx & 127;
        int b = m / HH, h = m % HH;
        int row = x * BSZ + b;
        int base = (h < 6) ? (row * 1536 + which * EH + h * 64)
                           : (row * 1536 + 3 * EH + (h - 6) * 64);
        const float* wv = attn_w + which * 64;
        v = g_proj[base + lane] * wv[lane] + g_proj[base + lane + 32] * wv[lane + 32];
    } else {
        int i = idx / BHH, s = idx % BHH;
        int b = s / HH, h = s % HH;
        int base = (i * BSZ + b) * EE + h * 64;
        v = entity[base + lane] * attn_w[128 + lane]
          + entity[base + lane + 32] * attn_w[128 + lane + 32];
    }
    #pragma unroll
    for (int off = 16; off; off >>= 1) v += __shfl_down_sync(0xffffffffu, v, off);
    if (lane == 0) {
        if (which == 0)      g_dq[idx] = v;
        else if (which == 1) g_dk[idx] = v;
        else                 g_de[idx] = v;
    }
}

// ---------------- fused scores + leakyrelu + softmax + probs@Ve -------------
__global__ __launch_bounds__(128)
void attn_kernel(const float* __restrict__ attn_b)
{
    __shared__ float sp[128];
    __shared__ float red[128];
    __shared__ float wred[4];
    const int i2 = blockIdx.x;
    const int bh = blockIdx.y;
    const int j  = threadIdx.x;
    const int lane = j & 31, w = j >> 5;

    const int g     = bh * (LL * LL) + i2 * LL + j;
    const int i_src = g / 3072;
    const int rem   = g % 3072;

    float score = g_dq[(rem % BHH) * LL + i_src]
                + g_dk[(rem >> 7) * LL + (rem & 127)]
                + g_de[i_src * BHH + (rem % BHH)]
                - g_de[(rem / BHH) * BHH + (rem % BHH)]
                + attn_b[0];
    score = (score >= 0.f) ? score : 0.01f * score;

    // max over 128 via warp shuffle + 4-way combine
    float m = score;
    #pragma unroll
    for (int off = 16; off; off >>= 1)
        m = fmaxf(m, __shfl_xor_sync(0xffffffffu, m, off));
    if (lane == 0) wred[w] = m;
    __syncthreads();
    float mx = fmaxf(fmaxf(wred[0], wred[1]), fmaxf(wred[2], wred[3]));

    float ex = __expf(score - mx);
    sp[j] = ex;
    float s = ex;
    #pragma unroll
    for (int off = 16; off; off >>= 1)
        s += __shfl_xor_sync(0xffffffffu, s, off);
    __syncthreads();            // all threads have read wred (mx); sp published
    if (lane == 0) wred[w] = s;
    __syncthreads();
    float inv = 1.f / (wred[0] + wred[1] + wred[2] + wred[3]);

    const int b = bh / HH, h = bh % HH;
    const int off = (h < 6) ? (2 * EH + h * 64) : (3 * EH + (h - 6) * 64);
    const int d = j & 63, half = j >> 6;
    float accv = 0.f;
    const int j0 = half * 64;
    #pragma unroll 8
    for (int jj = j0; jj < j0 + 64; jj++) {
        accv += sp[jj] * g_proj[(jj * BSZ + b) * 1536 + off + d];
    }
    red[j] = accv; __syncthreads();
    if (j < 64) {
        float total = (red[j] + red[j + 64]) * inv;
        g_a[(i2 * BSZ + b) * EE + h * 64 + d] = total;
    }
}

// ---------------- launcher ---------------------------------------------------
extern "C" void kernel_launch(void* const* d_in, const int* in_sizes, int n_in,
                              void* d_out, int out_size)
{
    const float* query    = (const float*)d_in[0];
    const float* entity   = (const float*)d_in[1];
    const float* conv_w   = (const float*)d_in[2];
    const float* conv_b   = (const float*)d_in[3];
    const float* q_w      = (const float*)d_in[4];
    const float* q_b      = (const float*)d_in[5];
    const float* k_w      = (const float*)d_in[6];
    const float* k_b      = (const float*)d_in[7];
    const float* v_w      = (const float*)d_in[8];
    const float* v_b      = (const float*)d_in[9];
    const float* e_w      = (const float*)d_in[10];
    const float* e_b      = (const float*)d_in[11];
    const float* attn_w   = (const float*)d_in[12];
    const float* attn_b   = (const float*)d_in[13];
    const float* deconv_w = (const float*)d_in[14];
    const float* deconv_b = (const float*)d_in[15];
    const float* out_w    = (const float*)d_in[16];
    const float* out_b    = (const float*)d_in[17];
    float* out = (float*)d_out;

    gemm_kernel<0><<<dim3(24, 4), 256>>>(query, conv_w, nullptr, nullptr, nullptr,
                                         conv_b, nullptr, nullptr, nullptr, nullptr);
    gemm_kernel<1><<<dim3(48, 4), 256>>>(entity, q_w, k_w, v_w, e_w,
                                         q_b, k_b, v_b, e_b, nullptr);
    dots_kernel<<<1152, 256>>>(entity, attn_w);
    attn_kernel<<<dim3(LL, BHH), 128>>>(attn_b);
    gemm_kernel<2><<<dim3(24, 4), 256>>>(nullptr, deconv_w, nullptr, nullptr, nullptr,
                                         deconv_b, nullptr, nullptr, nullptr, nullptr);
    gemm_kernel<3><<<dim3(24, 4), 256>>>(nullptr, out_w, nullptr, nullptr, nullptr,
                                         out_b, nullptr, nullptr, nullptr, out);
}

// round 5
// speedup vs baseline: 2.8272x; 1.1241x over previous
#include <cuda_runtime.h>

#define LL   128
#define BSZ  2
#define EE   768
#define HH   12
#define EH   384              // E/2
#define BHH  24               // B*H

// ---------------- scratch (device globals; no allocation allowed) -----------
__device__ float g_nq[256 * EE];            // conv1d(query) output, (L,B,E)
__device__ float g_proj[256 * 4 * EH];      // [q | k | v | e] per row, (256,1536)
__device__ float g_dq[BHH * LL];
__device__ float g_dk[BHH * LL];
__device__ float g_de[LL * BHH];
__device__ float g_a[256 * EE];             // attention output in (L,B,E)
__device__ float g_y[256 * EE];             // deconv output

// ---------------- packed f32x2 helpers --------------------------------------
#define FMA2(d, a, b) asm("fma.rn.f32x2 %0, %1, %2, %3;" \
                          : "=l"(d) : "l"(a), "l"(b), "l"(d))
#define DUP2(d, s)    asm("mov.b64 %0, {%1, %1};" : "=l"(d) : "f"(s))
#define PACK2(d, lo, hi) asm("mov.b64 %0, {%1, %2};" : "=l"(d) : "f"(lo), "f"(hi))
#define UNPK(lo, hi, s) asm("mov.b64 {%0, %1}, %2;" : "=f"(lo), "=f"(hi) : "l"(s))

// ---------------- init: zero the atomic-accumulation targets -----------------
__global__ __launch_bounds__(256)
void init_kernel(float* __restrict__ out)
{
    const int idx = blockIdx.x * 256 + threadIdx.x;   // 147456 float4 total
    float4 z = {0.f, 0.f, 0.f, 0.f};
    if (idx < 49152)            ((float4*)g_nq)[idx] = z;
    else if (idx < 98304)       ((float4*)g_y)[idx - 49152] = z;
    else                        ((float4*)out)[idx - 98304] = z;
}

// ---------------- double-buffered f32x2 SGEMM, BK=32, optional K-split -------
// 256 threads, tile 64x32. acc rows-packed: acc[rp][c] over rows (ty*4+2rp, +1)
// MODE 0: nq   = conv(query)      M=256 N=768  K=1536  KSPLIT=2
// MODE 1: proj = [q|k|v|e]        M=256 N=1536 K=768   KSPLIT=1
// MODE 2: y    = deconv(a)        M=256 N=768  K=1536  KSPLIT=2
// MODE 3: out  = y @ out_w^T      M=256 N=768  K=768   KSPLIT=2
template<int MODE, int KSPLIT>
__global__ __launch_bounds__(256)
void gemm_kernel(const float* __restrict__ A0,
                 const float* __restrict__ W0,
                 const float* __restrict__ W1,
                 const float* __restrict__ W2,
                 const float* __restrict__ W3,
                 const float* __restrict__ bb0,
                 const float* __restrict__ bb1,
                 const float* __restrict__ bb2,
                 const float* __restrict__ bb3,
                 float* __restrict__ Cout)
{
    constexpr int BM = 64, BN = 32, BK = 32;
    constexpr int N  = (MODE == 1) ? 1536 : 768;
    constexpr int K  = (MODE == 0 || MODE == 2) ? 1536 : 768;
    constexpr int NT = K / KSPLIT / BK;
    constexpr int ASTR = BM + 4;   // 68: 16B-aligned rows, conflict-free LDS.128
    constexpr int BSTR = BN + 2;   // 34: 8B-aligned rows

    __shared__ __align__(16) float As[2][BK][ASTR];
    __shared__ __align__(16) float Bs[2][BK][BSTR];

    const int bn   = blockIdx.x * BN;
    const int bm   = blockIdx.y * BM;
    const int koff = (KSPLIT == 2) ? blockIdx.z * (K / 2) : 0;
    const int tid  = threadIdx.x;
    const int tx   = tid & 15;     // 16 col-groups * 2 cols
    const int ty   = tid >> 4;     // 16 row-groups * 4 rows

    // loader coordinates
    const int aKK = tid & 31;            // A: k within tile
    const int aTY = tid >> 5;            // A: row fragment 0..7
    const int bKK = tid & 31;            // B (modes 0,1,3): k
    const int bTY = tid >> 5;            // o fragment 0..7
    const int bO2 = tid & 31;            // B (mode 2): o
    const int bK2 = tid >> 5;            // k fragment 0..7

    float ar[8], br[4];

    auto loadA = [&](int t) {
        const int k = koff + t * BK + aKK;
        #pragma unroll
        for (int i = 0; i < 8; i++) {
            const int row = bm + i * 8 + aTY;
            float v;
            if (MODE == 0) {
                if (k < EE) v = (row >= BSZ) ? A0[(row - BSZ) * EE + k] : 0.f;
                else        v = A0[row * EE + (k - EE)];
            } else if (MODE == 1) {
                const float* Ap = (bn >= 3 * EH) ? A0 : g_nq;
                v = Ap[row * EE + k];
            } else if (MODE == 2) {
                if (k < EE) v = g_a[row * EE + k];
                else        v = (row >= BSZ) ? g_a[(row - BSZ) * EE + (k - EE)] : 0.f;
            } else {
                v = g_y[row * EE + k];
            }
            ar[i] = v;
        }
    };

    auto loadB = [&](int t) {
        if (MODE == 2) {
            const int o = bn + bO2;
            #pragma unroll
            for (int i = 0; i < 4; i++) {
                const int k = koff + t * BK + i * 8 + bK2;
                br[i] = (k < EE) ? W0[(k * EE + o) * 2]
                                 : W0[((k - EE) * EE + o) * 2 + 1];
            }
        } else {
            const int k = koff + t * BK + bKK;
            #pragma unroll
            for (int i = 0; i < 4; i++) {
                const int o = bn + i * 8 + bTY;
                float v;
                if (MODE == 0) {
                    v = (k < EE) ? W0[(o * EE + k) * 2]
                                 : W0[(o * EE + (k - EE)) * 2 + 1];
                } else if (MODE == 1) {
                    if (o < EH)          v = W0[o * EE + k];
                    else if (o < 2 * EH) v = W1[(o - EH) * EE + k];
                    else if (o < 3 * EH) v = W2[(o - 2 * EH) * EE + k];
                    else                 v = W3[(o - 3 * EH) * EE + k];
                } else {
                    v = W0[o * EE + k];
                }
                br[i] = v;
            }
        }
    };

    auto storeTiles = [&](int nb) {
        #pragma unroll
        for (int i = 0; i < 8; i++) As[nb][aKK][i * 8 + aTY] = ar[i];
        if (MODE == 2) {
            #pragma unroll
            for (int i = 0; i < 4; i++) Bs[nb][i * 8 + bK2][bO2] = br[i];
        } else {
            #pragma unroll
            for (int i = 0; i < 4; i++) Bs[nb][bKK][i * 8 + bTY] = br[i];
        }
    };

    unsigned long long acc[2][2] = {};

    loadA(0); loadB(0);
    storeTiles(0);
    __syncthreads();

    int buf = 0;
    for (int t = 0; t < NT; t++) {
        if (t + 1 < NT) { loadA(t + 1); loadB(t + 1); }

        #pragma unroll
        for (int kk = 0; kk < BK; kk++) {
            const ulonglong2 av = *(const ulonglong2*)&As[buf][kk][ty * 4];
            const float b0 = Bs[buf][kk][tx * 2];
            const float b1 = Bs[buf][kk][tx * 2 + 1];
            unsigned long long bd0, bd1;
            DUP2(bd0, b0); DUP2(bd1, b1);
            FMA2(acc[0][0], av.x, bd0);
            FMA2(acc[0][1], av.x, bd1);
            FMA2(acc[1][0], av.y, bd0);
            FMA2(acc[1][1], av.y, bd1);
        }

        if (t + 1 < NT) {
            storeTiles(buf ^ 1);
            __syncthreads();
            buf ^= 1;
        }
    }

    // ---- epilogue -------------------------------------------------------------
    float* C = (MODE == 0) ? g_nq : (MODE == 1) ? g_proj
             : (MODE == 2) ? g_y  : Cout;
    const int oB = bn + tx * 2;
    float bias0, bias1;
    if (MODE == 1) {
        const int seg = oB / EH;                       // 0..3 (EH not pow2!)
        const float* bp = (seg == 0) ? bb0 : (seg == 1) ? bb1
                        : (seg == 2) ? bb2 : bb3;
        const int ob = oB - seg * EH;
        bias0 = bp[ob]; bias1 = bp[ob + 1];
    } else {
        bias0 = bb0[oB]; bias1 = bb0[oB + 1];
    }
    if (KSPLIT == 2 && blockIdx.z != 0) { bias0 = 0.f; bias1 = 0.f; }

    #pragma unroll
    for (int rp = 0; rp < 2; rp++) {
        float c0lo, c0hi, c1lo, c1hi;
        UNPK(c0lo, c0hi, acc[rp][0]);
        UNPK(c1lo, c1hi, acc[rp][1]);
        const int r0 = bm + ty * 4 + rp * 2;
        if (KSPLIT == 1) {
            float2 v0 = {c0lo + bias0, c1lo + bias1};
            float2 v1 = {c0hi + bias0, c1hi + bias1};
            *(float2*)&C[r0 * N + oB]       = v0;
            *(float2*)&C[(r0 + 1) * N + oB] = v1;
        } else {
            atomicAdd(&C[r0 * N + oB],           c0lo + bias0);
            atomicAdd(&C[r0 * N + oB + 1],       c1lo + bias1);
            atomicAdd(&C[(r0 + 1) * N + oB],     c0hi + bias0);
            atomicAdd(&C[(r0 + 1) * N + oB + 1], c1hi + bias1);
        }
    }
}

// ---------------- dq / dk / de precompute (9216 length-64 dots) -------------
__global__ __launch_bounds__(256)
void dots_kernel(const float* __restrict__ entity,
                 const float* __restrict__ attn_w)
{
    int w    = (blockIdx.x * blockDim.x + threadIdx.x) >> 5;
    int lane = threadIdx.x & 31;
    if (w >= 3 * BHH * LL) return;
    int which = w / (BHH * LL);
    int idx   = w % (BHH * LL);
    float v;
    if (which < 2) {
        int m = idx >> 7, x = idx & 127;
        int b = m / HH, h = m % HH;
        int row = x * BSZ + b;
        int base = (h < 6) ? (row * 1536 + which * EH + h * 64)
                           : (row * 1536 + 3 * EH + (h - 6) * 64);
        const float* wv = attn_w + which * 64;
        v = g_proj[base + lane] * wv[lane] + g_proj[base + lane + 32] * wv[lane + 32];
    } else {
        int i = idx / BHH, s = idx % BHH;
        int b = s / HH, h = s % HH;
        int base = (i * BSZ + b) * EE + h * 64;
        v = entity[base + lane] * attn_w[128 + lane]
          + entity[base + lane + 32] * attn_w[128 + lane + 32];
    }
    #pragma unroll
    for (int off = 16; off; off >>= 1) v += __shfl_down_sync(0xffffffffu, v, off);
    if (lane == 0) {
        if (which == 0)      g_dq[idx] = v;
        else if (which == 1) g_dk[idx] = v;
        else                 g_de[idx] = v;
    }
}

// ---------------- fused attention: 16 rows per block ------------------------
// score(g) = dq[(rem%24)*128+i_src] + dk[rem] + de[i_src*24+rem%24] - de[rem]
//          = sqe[i_loc*24 + rem%24] + sT[rem] + bias   (i_loc = i_src - i_src0)
__global__ __launch_bounds__(256)
void attn_kernel(const float* __restrict__ attn_b)
{
    __shared__ float sT[3072];       // dk - de
    __shared__ float sqe[64];        // dq + de for the block's 2 i_src values
    __shared__ __align__(8) float sp[16][128];   // normalized probs

    const int ig  = blockIdx.x;      // 0..7 (16-row group)
    const int bh  = blockIdx.y;      // 0..23
    const int tid = threadIdx.x;
    const int g0  = bh * 16384 + ig * 2048;
    const int i_src0 = g0 / 3072;

    // ---- phase A: tables ----
    for (int x = tid; x < 3072; x += 256) sT[x] = g_dk[x] - g_de[x];
    if (tid < 48) {
        const int il = tid / 24, s = tid - il * 24;
        const int isrc = min(i_src0 + il, LL - 1);
        sqe[tid] = g_dq[s * 128 + isrc] + g_de[isrc * 24 + s];
    }
    __syncthreads();
    const float bias = attn_b[0];

    // ---- phase B: scores + softmax, warp w owns rows w and w+8 ----
    const int lane = tid & 31, w = tid >> 5;
    #pragma unroll
    for (int rr = 0; rr < 2; rr++) {
        const int r  = w + rr * 8;
        const int gb = g0 + r * 128;
        float sc[4];
        #pragma unroll
        for (int q = 0; q < 4; q++) {
            const int g    = gb + q * 32 + lane;
            const int isrc = g / 3072;
            const int rem  = g - isrc * 3072;
            const int s    = rem % 24;
            float v = sqe[(isrc - i_src0) * 24 + s] + sT[rem] + bias;
            sc[q] = (v >= 0.f) ? v : 0.01f * v;
        }
        float m = fmaxf(fmaxf(sc[0], sc[1]), fmaxf(sc[2], sc[3]));
        #pragma unroll
        for (int off = 16; off; off >>= 1)
            m = fmaxf(m, __shfl_xor_sync(0xffffffffu, m, off));
        float e[4], sum = 0.f;
        #pragma unroll
        for (int q = 0; q < 4; q++) { e[q] = __expf(sc[q] - m); sum += e[q]; }
        #pragma unroll
        for (int off = 16; off; off >>= 1)
            sum += __shfl_xor_sync(0xffffffffu, sum, off);
        const float inv = 1.f / sum;
        #pragma unroll
        for (int q = 0; q < 4; q++) sp[r][q * 32 + lane] = e[q] * inv;
    }
    __syncthreads();

    // ---- phase C: probs(16x128) @ Ve(128x64) ----
    const int b = bh / HH, h = bh - (bh / HH) * HH;
    const int off = (h < 6) ? (2 * EH + h * 64) : (3 * EH + (h - 6) * 64);
    const int d  = tid & 63;
    const int r0 = (tid >> 6) * 4;   // 0,4,8,12
    const float* Vp = g_proj + b * 1536 + off + d;   // element jj at Vp[jj*3072]

    unsigned long long acc2[4] = {};
    #pragma unroll 4
    for (int jj = 0; jj < 128; jj += 2) {
        const float v0 = Vp[jj * 3072];
        const float v1 = Vp[(jj + 1) * 3072];
        unsigned long long vv;
        PACK2(vv, v0, v1);
        #pragma unroll
        for (int r = 0; r < 4; r++) {
            const unsigned long long pp = *(const unsigned long long*)&sp[r0 + r][jj];
            FMA2(acc2[r], pp, vv);
        }
    }
    #pragma unroll
    for (int r = 0; r < 4; r++) {
        float lo, hi;
        UNPK(lo, hi, acc2[r]);
        const int i2 = ig * 16 + r0 + r;
        g_a[(i2 * BSZ + b) * EE + h * 64 + d] = lo + hi;
    }
}

// ---------------- launcher ---------------------------------------------------
extern "C" void kernel_launch(void* const* d_in, const int* in_sizes, int n_in,
                              void* d_out, int out_size)
{
    const float* query    = (const float*)d_in[0];
    const float* entity   = (const float*)d_in[1];
    const float* conv_w   = (const float*)d_in[2];
    const float* conv_b   = (const float*)d_in[3];
    const float* q_w      = (const float*)d_in[4];
    const float* q_b      = (const float*)d_in[5];
    const float* k_w      = (const float*)d_in[6];
    const float* k_b      = (const float*)d_in[7];
    const float* v_w      = (const float*)d_in[8];
    const float* v_b      = (const float*)d_in[9];
    const float* e_w      = (const float*)d_in[10];
    const float* e_b      = (const float*)d_in[11];
    const float* attn_w   = (const float*)d_in[12];
    const float* attn_b   = (const float*)d_in[13];
    const float* deconv_w = (const float*)d_in[14];
    const float* deconv_b = (const float*)d_in[15];
    const float* out_w    = (const float*)d_in[16];
    const float* out_b    = (const float*)d_in[17];
    float* out = (float*)d_out;

    init_kernel<<<576, 256>>>(out);
    gemm_kernel<0, 2><<<dim3(24, 4, 2), 256>>>(query, conv_w, nullptr, nullptr, nullptr,
                                               conv_b, nullptr, nullptr, nullptr, nullptr);
    gemm_kernel<1, 1><<<dim3(48, 4, 1), 256>>>(entity, q_w, k_w, v_w, e_w,
                                               q_b, k_b, v_b, e_b, nullptr);
    dots_kernel<<<1152, 256>>>(entity, attn_w);
    attn_kernel<<<dim3(8, BHH), 256>>>(attn_b);
    gemm_kernel<2, 2><<<dim3(24, 4, 2), 256>>>(nullptr, deconv_w, nullptr, nullptr, nullptr,
                                               deconv_b, nullptr, nullptr, nullptr, nullptr);
    gemm_kernel<3, 2><<<dim3(24, 4, 2), 256>>>(nullptr, out_w, nullptr, nullptr, nullptr,
                                               out_b, nullptr, nullptr, nullptr, out);
}